// round 4
// baseline (speedup 1.0000x reference)
#include <cuda_runtime.h>
#include <math.h>

#define H 128
#define MAXB 8192

// segment start offsets (allocation-free scratch)
__device__ int g_starts[MAXB + 1];

// ---------------------------------------------------------------------------
// Kernel 0: build segment start offsets from sorted segment_ids.
// ---------------------------------------------------------------------------
__global__ __launch_bounds__(256) void seg_starts_kernel(
    const int* __restrict__ seg_ids, int T, int B)
{
    const int i = blockIdx.x * blockDim.x + threadIdx.x;
    if (i >= T) return;
    const int cur  = seg_ids[i];
    const int prev = (i == 0) ? -1 : seg_ids[i - 1];
    for (int s = prev + 1; s <= cur; s++) g_starts[s] = i;
    if (i == T - 1)
        for (int s = cur + 1; s <= B; s++) g_starts[s] = T;
}

// ---------------------------------------------------------------------------
// Fused: gather + segment-mean + MLP head + BCE. One CTA per segment.
// All global traffic is LDG.128:
//  - gather: warp w sums full rows of its token subset (lane l -> dims 4l..4l+3)
//  - matvec: warp w covers k in [32w, 32w+32), lane l -> output dims 4l..4l+3
// Cross-warp combines go through 2KB shared.
// ---------------------------------------------------------------------------
__global__ __launch_bounds__(128) void fused_dan_kernel(
    const int*   __restrict__ token_ids,
    const float* __restrict__ embed,
    const float* __restrict__ y_true,
    const float* __restrict__ W_hid,   // [H, H] row-major
    const float* __restrict__ b_hid,   // [H]
    const float* __restrict__ W_out,   // [H]
    const float* __restrict__ b_out,   // [1]
    float*       __restrict__ out,
    int B)
{
    const int seg = blockIdx.x;
    const int tid = threadIdx.x;
    const int w   = tid >> 5;
    const int l   = tid & 31;

    const int start = g_starts[seg];
    const int end   = g_starts[seg + 1];

    __shared__ int   s_tok[128];
    __shared__ float s_part[4 * H];   // per-warp partials (reused in both phases)
    __shared__ float s_vec[H];        // sentence mean
    __shared__ float s_red[4];

    const float4* E4 = (const float4*)embed;   // row = 32 float4

    // ---- gather: warp-per-row float4 loads ----
    float4 a0 = make_float4(0.f, 0.f, 0.f, 0.f), a1 = a0, a2 = a0, a3 = a0;

    for (int t0 = start; t0 < end; t0 += 128) {
        const int n = min(128, end - t0);
        __syncthreads();
        if (tid < n) s_tok[tid] = token_ids[t0 + tid];
        __syncthreads();
        const int lo = w * 32;
        const int hi = min(n, lo + 32);
        int i = lo;
        for (; i + 4 <= hi; i += 4) {
            const float4 r0 = __ldg(&E4[(size_t)s_tok[i + 0] * 32 + l]);
            const float4 r1 = __ldg(&E4[(size_t)s_tok[i + 1] * 32 + l]);
            const float4 r2 = __ldg(&E4[(size_t)s_tok[i + 2] * 32 + l]);
            const float4 r3 = __ldg(&E4[(size_t)s_tok[i + 3] * 32 + l]);
            a0.x += r0.x; a0.y += r0.y; a0.z += r0.z; a0.w += r0.w;
            a1.x += r1.x; a1.y += r1.y; a1.z += r1.z; a1.w += r1.w;
            a2.x += r2.x; a2.y += r2.y; a2.z += r2.z; a2.w += r2.w;
            a3.x += r3.x; a3.y += r3.y; a3.z += r3.z; a3.w += r3.w;
        }
        for (; i < hi; i++) {
            const float4 r = __ldg(&E4[(size_t)s_tok[i] * 32 + l]);
            a0.x += r.x; a0.y += r.y; a0.z += r.z; a0.w += r.w;
        }
    }

    float4 asum;
    asum.x = (a0.x + a1.x) + (a2.x + a3.x);
    asum.y = (a0.y + a1.y) + (a2.y + a3.y);
    asum.z = (a0.z + a1.z) + (a2.z + a3.z);
    asum.w = (a0.w + a1.w) + (a2.w + a3.w);
    *(float4*)&s_part[w * H + 4 * l] = asum;
    __syncthreads();

    const float inv = 1.0f / (float)max(end - start, 1);
    s_vec[tid] = ((s_part[tid] + s_part[H + tid]) +
                  (s_part[2 * H + tid] + s_part[3 * H + tid])) * inv;
    __syncthreads();   // also protects s_part before reuse below

    // ---- matvec: warp w covers k in [32w, 32w+32); lane l -> outputs 4l..4l+3 ----
    const float4* W4  = (const float4*)W_hid;       // W4[k*32 + c] = W[k][4c..4c+3]
    const float4* SV4 = (const float4*)s_vec;
    float4 acc = make_float4(0.f, 0.f, 0.f, 0.f);

#pragma unroll
    for (int kk = 0; kk < 32; kk += 4) {
        const int k = w * 32 + kk;
        const float4 s4 = SV4[k >> 2];
        const float4 w0 = __ldg(&W4[(k + 0) * 32 + l]);
        const float4 w1 = __ldg(&W4[(k + 1) * 32 + l]);
        const float4 w2 = __ldg(&W4[(k + 2) * 32 + l]);
        const float4 w3 = __ldg(&W4[(k + 3) * 32 + l]);
        acc.x += s4.x * w0.x + s4.y * w1.x + s4.z * w2.x + s4.w * w3.x;
        acc.y += s4.x * w0.y + s4.y * w1.y + s4.z * w2.y + s4.w * w3.y;
        acc.z += s4.x * w0.z + s4.y * w1.z + s4.z * w2.z + s4.w * w3.z;
        acc.w += s4.x * w0.w + s4.y * w1.w + s4.z * w2.w + s4.w * w3.w;
    }
    *(float4*)&s_part[w * H + 4 * l] = acc;
    __syncthreads();

    // thread tid owns output dim tid
    const float hid = ((s_part[tid] + s_part[H + tid]) +
                       (s_part[2 * H + tid] + s_part[3 * H + tid])) + b_hid[tid];
    float val = tanhf(hid) * W_out[tid];

#pragma unroll
    for (int off = 16; off > 0; off >>= 1)
        val += __shfl_xor_sync(0xffffffffu, val, off);
    if (l == 0) s_red[w] = val;
    __syncthreads();

    if (tid == 0) {
        const float z = (s_red[0] + s_red[1]) + (s_red[2] + s_red[3]) + __ldg(b_out);
        const float lp  = fmaxf(-log1pf(expf(-z)), -100.0f);
        const float l1m = fmaxf(-log1pf(expf(z)),  -100.0f);
        const float y   = y_true[seg];
        atomicAdd(out, -(y * lp + (1.0f - y) * l1m));
    }
}

// ---------------------------------------------------------------------------
extern "C" void kernel_launch(void* const* d_in, const int* in_sizes, int n_in,
                              void* d_out, int out_size)
{
    const int*   token_ids = (const int*)d_in[0];
    const int*   seg_ids   = (const int*)d_in[1];
    const float* y_true    = (const float*)d_in[2];
    const float* embed     = (const float*)d_in[3];
    const float* W_hid     = (const float*)d_in[4];
    const float* b_hid     = (const float*)d_in[5];
    const float* W_out     = (const float*)d_in[6];
    const float* b_out     = (const float*)d_in[7];

    const int T = in_sizes[0];
    const int B = in_sizes[2];
    float* out = (float*)d_out;

    cudaMemsetAsync(out, 0, sizeof(float));

    seg_starts_kernel<<<(T + 255) / 256, 256>>>(seg_ids, T, B);

    fused_dan_kernel<<<B, 128>>>(token_ids, embed, y_true,
                                 W_hid, b_hid, W_out, b_out, out, B);
}

// round 5
// speedup vs baseline: 1.0507x; 1.0507x over previous
#include <cuda_runtime.h>
#include <math.h>

#define H 128
#define MAXB 8192
#define RPB 16   // rows per block in the MLP kernel

__device__ int   g_starts[MAXB + 1];
__device__ float g_sent[(size_t)MAXB * H];

// ---------------------------------------------------------------------------
// Kernel 0: segment start offsets from sorted segment_ids.
// ---------------------------------------------------------------------------
__global__ __launch_bounds__(256) void seg_starts_kernel(
    const int* __restrict__ seg_ids, int T, int B)
{
    const int i = blockIdx.x * blockDim.x + threadIdx.x;
    if (i >= T) return;
    const int cur  = seg_ids[i];
    const int prev = (i == 0) ? -1 : seg_ids[i - 1];
    for (int s = prev + 1; s <= cur; s++) g_starts[s] = i;
    if (i == T - 1)
        for (int s = cur + 1; s <= B; s++) g_starts[s] = T;
}

// ---------------------------------------------------------------------------
// Kernel 1: gather + segment mean. CTA per segment; warp w takes tokens
// i = w, w+4, w+8, ... (balanced for any segment length); lane l holds
// embedding dims 4l..4l+3 as float4 (pure LDG.128 traffic).
// ---------------------------------------------------------------------------
__global__ __launch_bounds__(128) void seg_mean_kernel(
    const int*   __restrict__ token_ids,
    const float* __restrict__ embed)
{
    const int seg = blockIdx.x;
    const int tid = threadIdx.x;
    const int w   = tid >> 5;
    const int l   = tid & 31;

    const int start = g_starts[seg];
    const int end   = g_starts[seg + 1];

    __shared__ int   s_tok[128];
    __shared__ float s_part[4 * H];

    const float4* E4 = (const float4*)embed;   // row = 32 float4

    float4 a0 = make_float4(0.f, 0.f, 0.f, 0.f), a1 = a0, a2 = a0, a3 = a0;

    for (int t0 = start; t0 < end; t0 += 128) {
        const int n = min(128, end - t0);
        __syncthreads();
        if (tid < n) s_tok[tid] = token_ids[t0 + tid];
        __syncthreads();
        int i = w;
        for (; i + 12 < n; i += 16) {        // 4 loads in flight per warp
            const float4 r0 = __ldg(&E4[(size_t)s_tok[i +  0] * 32 + l]);
            const float4 r1 = __ldg(&E4[(size_t)s_tok[i +  4] * 32 + l]);
            const float4 r2 = __ldg(&E4[(size_t)s_tok[i +  8] * 32 + l]);
            const float4 r3 = __ldg(&E4[(size_t)s_tok[i + 12] * 32 + l]);
            a0.x += r0.x; a0.y += r0.y; a0.z += r0.z; a0.w += r0.w;
            a1.x += r1.x; a1.y += r1.y; a1.z += r1.z; a1.w += r1.w;
            a2.x += r2.x; a2.y += r2.y; a2.z += r2.z; a2.w += r2.w;
            a3.x += r3.x; a3.y += r3.y; a3.z += r3.z; a3.w += r3.w;
        }
        for (; i < n; i += 4) {
            const float4 r = __ldg(&E4[(size_t)s_tok[i] * 32 + l]);
            a0.x += r.x; a0.y += r.y; a0.z += r.z; a0.w += r.w;
        }
    }

    float4 asum;
    asum.x = (a0.x + a1.x) + (a2.x + a3.x);
    asum.y = (a0.y + a1.y) + (a2.y + a3.y);
    asum.z = (a0.z + a1.z) + (a2.z + a3.z);
    asum.w = (a0.w + a1.w) + (a2.w + a3.w);
    *(float4*)&s_part[w * H + 4 * l] = asum;
    __syncthreads();

    const float inv = 1.0f / (float)max(end - start, 1);
    g_sent[(size_t)seg * H + tid] =
        ((s_part[tid] + s_part[H + tid]) +
         (s_part[2 * H + tid] + s_part[3 * H + tid])) * inv;
}

// ---------------------------------------------------------------------------
// Kernel 2: batched GEMV + tanh + dot(W_out) + BCE. 16 rows per 256-thread
// block -> 16x less W traffic than the fused version. Thread t owns output
// column (t&127) for the 8 rows of its half (t>>7). Sentence tile is staged
// transposed in smem so the k-loop is 1 LDG + 2 broadcast LDS.128 + 8 FMA.
// ---------------------------------------------------------------------------
__global__ __launch_bounds__(256) void mlp_bce_kernel(
    const float* __restrict__ y_true,
    const float* __restrict__ W_hid,   // [H,H] row-major
    const float* __restrict__ b_hid,
    const float* __restrict__ W_out,
    const float* __restrict__ b_out,
    float*       __restrict__ out,
    int B)
{
    const int t    = threadIdx.x;
    const int row0 = blockIdx.x * RPB;

    __shared__ float s_t[H][RPB];      // transposed sentence tile (8 KB)
    __shared__ float red[2][8][4];     // [grp][local row][warp-in-grp]

    for (int e = t; e < RPB * H; e += 256) {
        const int r = e >> 7;          // 0..15
        const int k = e & 127;
        const int row = min(row0 + r, B - 1);
        s_t[k][r] = g_sent[(size_t)row * H + k];
    }
    __syncthreads();

    const int col = t & 127;
    const int grp = t >> 7;            // 0/1: local rows grp*8 .. grp*8+7

    float acc[8];
    const float bh = b_hid[col];
#pragma unroll
    for (int r = 0; r < 8; r++) acc[r] = bh;

#pragma unroll 4
    for (int k = 0; k < H; k++) {
        const float  wv = __ldg(&W_hid[k * H + col]);
        const float4 sa = *(const float4*)&s_t[k][grp * 8 + 0];   // broadcast
        const float4 sb = *(const float4*)&s_t[k][grp * 8 + 4];
        acc[0] += sa.x * wv;  acc[1] += sa.y * wv;
        acc[2] += sa.z * wv;  acc[3] += sa.w * wv;
        acc[4] += sb.x * wv;  acc[5] += sb.y * wv;
        acc[6] += sb.z * wv;  acc[7] += sb.w * wv;
    }

    const float wo = W_out[col];
    float val[8];
#pragma unroll
    for (int r = 0; r < 8; r++)
        val[r] = tanhf(acc[r]) * wo;

#pragma unroll
    for (int off = 16; off > 0; off >>= 1)
#pragma unroll
        for (int r = 0; r < 8; r++)
            val[r] += __shfl_xor_sync(0xffffffffu, val[r], off);

    const int lane = t & 31;
    const int wig  = (t >> 5) & 3;     // warp index within its 128-thread group
    if (lane == 0)
#pragma unroll
        for (int r = 0; r < 8; r++) red[grp][r][wig] = val[r];
    __syncthreads();

    if (t < RPB) {
        const int g  = t >> 3;
        const int rr = t & 7;
        const int row = row0 + t;
        float loss = 0.f;
        if (row < B) {
            const float z = (red[g][rr][0] + red[g][rr][1]) +
                            (red[g][rr][2] + red[g][rr][3]) + __ldg(b_out);
            const float lp  = fmaxf(-log1pf(expf(-z)), -100.0f);
            const float l1m = fmaxf(-log1pf(expf(z)),  -100.0f);
            const float y   = y_true[row];
            loss = -(y * lp + (1.0f - y) * l1m);
        }
#pragma unroll
        for (int off = 8; off > 0; off >>= 1)
            loss += __shfl_xor_sync(0x0000ffffu, loss, off);
        if (t == 0) atomicAdd(out, loss);
    }
}

// ---------------------------------------------------------------------------
extern "C" void kernel_launch(void* const* d_in, const int* in_sizes, int n_in,
                              void* d_out, int out_size)
{
    const int*   token_ids = (const int*)d_in[0];
    const int*   seg_ids   = (const int*)d_in[1];
    const float* y_true    = (const float*)d_in[2];
    const float* embed     = (const float*)d_in[3];
    const float* W_hid     = (const float*)d_in[4];
    const float* b_hid     = (const float*)d_in[5];
    const float* W_out     = (const float*)d_in[6];
    const float* b_out     = (const float*)d_in[7];

    const int T = in_sizes[0];
    const int B = in_sizes[2];
    float* out = (float*)d_out;

    cudaMemsetAsync(out, 0, sizeof(float));

    seg_starts_kernel<<<(T + 255) / 256, 256>>>(seg_ids, T, B);

    seg_mean_kernel<<<B, 128>>>(token_ids, embed);

    mlp_bce_kernel<<<(B + RPB - 1) / RPB, 256>>>(y_true, W_hid, b_hid,
                                                 W_out, b_out, out, B);
}